// round 4
// baseline (speedup 1.0000x reference)
#include <cuda_runtime.h>
#include <cstdint>

// CodeBook VQ argmin:
//   z:   (t=16, a=256, b=64, c=64) fp32   -> X[m][k], m = t*4096 + (b*64+c), k = a
//        element X[m][k] = z[ t*256*4096 + k*4096 + n ]  (pixel dim innermost: coalesced)
//   emb: (1024, 256) fp32
//   out: codes (16,64,64), argmin_k ( e2[k] - 2 * dot(X[m], emb[k]) )
//        written as FLOAT32 values (0.0 .. 1023.0) — rel_err == 1.0 exactly on the
//        prior int32 writes indicates the harness compares the output as float32
//        (int codes reinterpret as denormals ~ 0).
//
// GEMM shape M=65536, N=1024, K=256 with fused argmin epilogue.

#define BM 64
#define BN 64
#define BKT 32
#define TM 4
#define TN 4
#define NCODES 1024
#define KDIM 256
#define NPIX 4096   // 64*64 pixels per t

__device__ float g_e2[NCODES];

__global__ void e2_kernel(const float* __restrict__ emb) {
    int k = blockIdx.x * blockDim.x + threadIdx.x;
    if (k < NCODES) {
        const float* row = emb + (size_t)k * KDIM;
        float s = 0.f;
#pragma unroll 8
        for (int i = 0; i < KDIM; i++) s += row[i] * row[i];
        g_e2[k] = s;
    }
}

__global__ __launch_bounds__(256, 4) void vq_kernel(
    const float* __restrict__ z,
    const float* __restrict__ emb,
    float* __restrict__ out)
{
    __shared__ __align__(16) float Xs[BKT][BM];       // 8 KB  : Xs[k][m]
    __shared__ __align__(16) float Es[BKT][BN + 4];   // 8.5KB : Es[k][n], row stride 68 floats (272B, 16B-aligned)

    const int tid = threadIdx.x;
    const int tx = tid & 15;            // code sub-tile
    const int ty = tid >> 4;            // pixel sub-tile

    const int mbase = blockIdx.x * BM;        // 64 pixels, always within one t (4096 % 64 == 0)
    const int t     = mbase >> 12;
    const int nb    = mbase & (NPIX - 1);
    const float* zt = z + (size_t)t * KDIM * NPIX + nb;

    float minv[TM];
    int   mini[TM];
#pragma unroll
    for (int i = 0; i < TM; i++) { minv[i] = 3.4e38f; mini[i] = 0; }

    for (int n0 = 0; n0 < NCODES; n0 += BN) {
        float acc[TM][TN];
#pragma unroll
        for (int i = 0; i < TM; i++)
#pragma unroll
            for (int j = 0; j < TN; j++) acc[i][j] = 0.f;

        for (int k0 = 0; k0 < KDIM; k0 += BKT) {
            // ---- load X tile: Xs[k][m] = zt[(k0+k)*4096 + m]; 2048 elems, 2 x float4 per thread
#pragma unroll
            for (int i = 0; i < 2; i++) {
                int l  = tid + i * 256;          // 0..511 float4 slots
                int k  = l >> 4;                 // 0..31
                int m4 = (l & 15) << 2;          // 0,4,...,60
                float4 v = *(const float4*)(zt + (size_t)(k0 + k) * NPIX + m4);
                *(float4*)(&Xs[k][m4]) = v;
            }
            // ---- load E tile (transposed): Es[k][n] = emb[(n0+n)*256 + k0+k]
#pragma unroll
            for (int i = 0; i < 2; i++) {
                int l  = tid + i * 256;          // 0..511 float4 slots
                int n  = l >> 3;                 // 0..63
                int k4 = (l & 7) << 2;           // 0,4,...,28
                float4 v = *(const float4*)(emb + (size_t)(n0 + n) * KDIM + k0 + k4);
                Es[k4 + 0][n] = v.x;
                Es[k4 + 1][n] = v.y;
                Es[k4 + 2][n] = v.z;
                Es[k4 + 3][n] = v.w;
            }
            __syncthreads();

#pragma unroll
            for (int k = 0; k < BKT; k++) {
                float4 xr = *(const float4*)(&Xs[k][ty * TM]);
                float4 er = *(const float4*)(&Es[k][tx * TN]);
                float xv[4] = {xr.x, xr.y, xr.z, xr.w};
                float ev[4] = {er.x, er.y, er.z, er.w};
#pragma unroll
                for (int i = 0; i < TM; i++)
#pragma unroll
                    for (int j = 0; j < TN; j++)
                        acc[i][j] += xv[i] * ev[j];
            }
            __syncthreads();
        }

        // ---- fused epilogue: d = e2[code] - 2*dot; running argmin (ascending code order
        //      with strict < keeps the lowest index on ties, matching jnp.argmin)
#pragma unroll
        for (int j = 0; j < TN; j++) {
            int code = n0 + tx * TN + j;
            float e2 = g_e2[code];
#pragma unroll
            for (int i = 0; i < TM; i++) {
                float d = fmaf(-2.f, acc[i][j], e2);
                if (d < minv[i]) { minv[i] = d; mini[i] = code; }
            }
        }
    }

    // ---- reduce across the 16 tx lanes (xor shuffles stay inside the 16-lane group)
#pragma unroll
    for (int off = 8; off > 0; off >>= 1) {
#pragma unroll
        for (int i = 0; i < TM; i++) {
            float ov = __shfl_xor_sync(0xffffffffu, minv[i], off);
            int   oi = __shfl_xor_sync(0xffffffffu, mini[i], off);
            if (ov < minv[i] || (ov == minv[i] && oi < mini[i])) {
                minv[i] = ov; mini[i] = oi;
            }
        }
    }

    if (tx == 0) {
#pragma unroll
        for (int i = 0; i < TM; i++)
            out[mbase + ty * TM + i] = (float)mini[i];   // write codes as float32
    }
}

extern "C" void kernel_launch(void* const* d_in, const int* in_sizes, int n_in,
                              void* d_out, int out_size) {
    // z is the strictly larger input buffer — robust to metadata ordering and
    // to bytes-vs-elements in in_sizes.
    const float* z;
    const float* emb;
    if (n_in >= 2 && in_sizes[1] > in_sizes[0]) {
        z   = (const float*)d_in[1];
        emb = (const float*)d_in[0];
    } else {
        z   = (const float*)d_in[0];
        emb = (const float*)d_in[n_in > 1 ? 1 : 0];
    }

    float* out = (float*)d_out;

    e2_kernel<<<4, 256>>>(emb);
    vq_kernel<<<65536 / BM, 256>>>(z, emb, out);
}

// round 5
// speedup vs baseline: 1.0833x; 1.0833x over previous
#include <cuda_runtime.h>
#include <cstdint>

// CodeBook VQ argmin, GEMM M=65536 N=1024 K=256, fused argmin epilogue.
// R5: 128x128 block tile, 8x8 micro-tile, packed fma.rn.f32x2 (FFMA2),
//     dup-stored X in smem (free packed operands + broadcast reads),
//     conflict-free E reads (split 16B chunks, row stride 132).

#define BM 128
#define BN 128
#define BKT 16
#define NCODES 1024
#define KDIM 256
#define NPIX 4096
#define ESTR 132            // Es row stride (floats): 528B, 16B-aligned, conflict-free reads

#define FFMA2(acc, a, b) \
    asm("fma.rn.f32x2 %0, %1, %2, %0;" : "+l"(acc) : "l"(a), "l"(b))

__device__ float g_e2[NCODES];

__global__ void e2_kernel(const float* __restrict__ emb) {
    int k = blockIdx.x * blockDim.x + threadIdx.x;
    if (k < NCODES) {
        const float* row = emb + (size_t)k * KDIM;
        float s = 0.f;
#pragma unroll 8
        for (int i = 0; i < KDIM; i++) s += row[i] * row[i];
        g_e2[k] = s;
    }
}

__global__ __launch_bounds__(256, 2) void vq_kernel(
    const float* __restrict__ z,
    const float* __restrict__ emb,
    float* __restrict__ out)
{
    __shared__ __align__(16) float Xs2[BKT][2 * BM];   // 16 KB: x values duplicated (x,x)
    __shared__ __align__(16) float Es[BKT][ESTR];      // 8.25 KB

    const int tid = threadIdx.x;
    const int tx = tid & 15;            // code group: codes tx*4..+3 and 64+tx*4..+3 per BN tile
    const int ty = tid >> 4;            // pixel group: pixels ty*8..ty*8+7

    const int mbase = blockIdx.x * BM;  // 128 pixels, within one t (4096 % 128 == 0)
    const int t     = mbase >> 12;
    const int nb    = mbase & (NPIX - 1);
    const float* zt = z + (size_t)t * KDIM * NPIX + nb;

    float minv[8];
    int   mini[8];
#pragma unroll
    for (int i = 0; i < 8; i++) { minv[i] = 3.4e38f; mini[i] = 0; }

    for (int n0 = 0; n0 < NCODES; n0 += BN) {
        unsigned long long acc[8][4];   // packed f32x2: 8 pixels x 4 code-pairs
#pragma unroll
        for (int i = 0; i < 8; i++)
#pragma unroll
            for (int j = 0; j < 4; j++) acc[i][j] = 0ULL;

        for (int k0 = 0; k0 < KDIM; k0 += BKT) {
            // ---- X tile: 16x128, stored duplicated: Xs2[k][2m]=(x,x)
#pragma unroll
            for (int i = 0; i < 2; i++) {
                int l  = tid + i * 256;          // 0..511 float4 slots
                int k  = l >> 5;                 // 0..15
                int m4 = (l & 31) << 2;          // 0,4,...,124
                float4 v = *(const float4*)(zt + (size_t)(k0 + k) * NPIX + m4);
                float4 d0 = make_float4(v.x, v.x, v.y, v.y);
                float4 d1 = make_float4(v.z, v.z, v.w, v.w);
                *(float4*)(&Xs2[k][2 * m4 + 0]) = d0;
                *(float4*)(&Xs2[k][2 * m4 + 4]) = d1;
            }
            // ---- E tile (transposed): Es[k][n] = emb[(n0+n)*256 + k0+k]
#pragma unroll
            for (int i = 0; i < 2; i++) {
                int l  = tid + i * 256;          // 0..511 float4 slots
                int n  = l >> 2;                 // 0..127
                int k4 = (l & 3) << 2;           // 0,4,8,12
                float4 v = *(const float4*)(emb + (size_t)(n0 + n) * KDIM + k0 + k4);
                Es[k4 + 0][n] = v.x;
                Es[k4 + 1][n] = v.y;
                Es[k4 + 2][n] = v.z;
                Es[k4 + 3][n] = v.w;
            }
            __syncthreads();

#pragma unroll
            for (int k = 0; k < BKT; k++) {
                // 8 dup-pairs of x (broadcast within 8-lane phases)
                const ulonglong2* xr = (const ulonglong2*)(&Xs2[k][ty * 16]);
                ulonglong2 xa = xr[0], xb = xr[1], xc = xr[2], xd = xr[3];
                unsigned long long xv[8] = { xa.x, xa.y, xb.x, xb.y,
                                             xc.x, xc.y, xd.x, xd.y };
                // 4 code-pairs: codes 4tx..4tx+3 and 64+4tx..64+4tx+3
                ulonglong2 ea = *(const ulonglong2*)(&Es[k][tx * 4]);
                ulonglong2 eb = *(const ulonglong2*)(&Es[k][64 + tx * 4]);
                unsigned long long ep[4] = { ea.x, ea.y, eb.x, eb.y };
#pragma unroll
                for (int i = 0; i < 8; i++)
#pragma unroll
                    for (int j = 0; j < 4; j++)
                        FFMA2(acc[i][j], xv[i], ep[j]);
            }
            __syncthreads();
        }

        // ---- epilogue: d = e2[code] - 2*dot; ascending code order within thread
        float e2v[8];
        int   codev[8];
#pragma unroll
        for (int j = 0; j < 4; j++) {
            codev[j]     = n0 + tx * 4 + j;
            codev[4 + j] = n0 + 64 + tx * 4 + j;
        }
#pragma unroll
        for (int j = 0; j < 8; j++) e2v[j] = __ldg(&g_e2[codev[j]]);

#pragma unroll
        for (int i = 0; i < 8; i++) {
#pragma unroll
            for (int jp = 0; jp < 4; jp++) {
                float lo, hi;
                asm("mov.b64 {%0,%1}, %2;" : "=f"(lo), "=f"(hi) : "l"(acc[i][jp]));
                int   cidx = (jp < 2) ? (jp * 2) : (4 + (jp - 2) * 2);
                float d0 = fmaf(-2.f, lo, e2v[cidx]);
                float d1 = fmaf(-2.f, hi, e2v[cidx + 1]);
                if (d0 < minv[i]) { minv[i] = d0; mini[i] = codev[cidx]; }
                if (d1 < minv[i]) { minv[i] = d1; mini[i] = codev[cidx + 1]; }
            }
        }
    }

    // ---- reduce across the 16 tx lanes
#pragma unroll
    for (int off = 8; off > 0; off >>= 1) {
#pragma unroll
        for (int i = 0; i < 8; i++) {
            float ov = __shfl_xor_sync(0xffffffffu, minv[i], off);
            int   oi = __shfl_xor_sync(0xffffffffu, mini[i], off);
            if (ov < minv[i] || (ov == minv[i] && oi < mini[i])) {
                minv[i] = ov; mini[i] = oi;
            }
        }
    }

    if (tx == 0) {
#pragma unroll
        for (int i = 0; i < 8; i++)
            out[mbase + ty * 8 + i] = (float)mini[i];
    }
}

extern "C" void kernel_launch(void* const* d_in, const int* in_sizes, int n_in,
                              void* d_out, int out_size) {
    const float* z;
    const float* emb;
    if (n_in >= 2 && in_sizes[1] > in_sizes[0]) {
        z   = (const float*)d_in[1];
        emb = (const float*)d_in[0];
    } else {
        z   = (const float*)d_in[0];
        emb = (const float*)d_in[n_in > 1 ? 1 : 0];
    }

    float* out = (float*)d_out;

    e2_kernel<<<4, 256>>>(emb);
    vq_kernel<<<65536 / BM, 256>>>(z, emb, out);
}

// round 7
// speedup vs baseline: 1.8507x; 1.7084x over previous
#include <cuda_runtime.h>
#include <cuda_fp16.h>
#include <cstdint>

// CodeBook VQ argmin via legacy tensor-core HMMA (mma.sync.m16n8k16, fp16 in / fp32 acc).
// fp16-split for exactness: S = Xhi*Ehi^T + Xlo*Ehi^T + Xhi*Elo^T  (error ~5e-6 << gaps)
//   z: (16,256,64,64) fp32 -> X[m][k], m = t*4096 + n (pixel innermost), k = channel
//   emb: (1024,256) fp32 ; out[m] (float32) = argmin_k ( e2[k] - 2*dot(X[m],emb[k]) )

#define NCODES 1024
#define KDIM   256
#define NPIX   4096
#define MCTA   128

#define ASTR   264              // A smem row stride in halves (528B): 8-row ldmatrix conflict-free
#define BSTR   72               // B smem row stride in halves (144B): conflict-free
#define BK     64               // k per B tile
#define KT     12               // 3 segments x 4 tiles of 64 = effective K' = 768

// smem byte offsets
#define AHI_OFF   0                       // 128*528  = 67584
#define ALO_OFF   67584
#define B0_OFF    135168                  // 128*144  = 18432
#define B1_OFF    153600
#define E2_OFF    172032                  // 4096
#define MK_OFF    176128                  // 128*8 = 1024
#define SMEM_SZ   177152

__device__ __align__(16) __half g_Ehi[NCODES * KDIM];
__device__ __align__(16) __half g_Elo[NCODES * KDIM];
__device__ float g_e2[NCODES];

__device__ __forceinline__ void ldmx4(uint32_t* r, uint32_t addr) {
    asm volatile("ldmatrix.sync.aligned.m8n8.x4.shared.b16 {%0,%1,%2,%3}, [%4];"
                 : "=r"(r[0]), "=r"(r[1]), "=r"(r[2]), "=r"(r[3]) : "r"(addr));
}
__device__ __forceinline__ void mma16816(float* c, const uint32_t* a, uint32_t b0, uint32_t b1) {
    asm volatile("mma.sync.aligned.m16n8k16.row.col.f32.f16.f16.f32 "
                 "{%0,%1,%2,%3}, {%4,%5,%6,%7}, {%8,%9}, {%0,%1,%2,%3};"
                 : "+f"(c[0]), "+f"(c[1]), "+f"(c[2]), "+f"(c[3])
                 : "r"(a[0]), "r"(a[1]), "r"(a[2]), "r"(a[3]), "r"(b0), "r"(b1));
}
__device__ __forceinline__ void cp16(uint32_t dst, const void* src) {
    asm volatile("cp.async.cg.shared.global [%0], [%1], 16;"
                 :: "r"(dst), "l"(__cvta_generic_to_global(src)) : "memory");
}
#define CP_COMMIT() asm volatile("cp.async.commit_group;" ::: "memory")
#define CP_WAIT1()  asm volatile("cp.async.wait_group 1;" ::: "memory")
#define CP_WAIT0()  asm volatile("cp.async.wait_group 0;" ::: "memory")

// ---------------- prep: split emb to fp16 hi/lo + e2 ----------------
__global__ void prep_split(const float* __restrict__ emb) {
    int i4 = (blockIdx.x * blockDim.x + threadIdx.x) * 4;
    float4 v = *(const float4*)(emb + i4);
    float vv[4] = {v.x, v.y, v.z, v.w};
    __half h[4], l[4];
#pragma unroll
    for (int j = 0; j < 4; j++) {
        h[j] = __float2half_rn(vv[j]);
        l[j] = __float2half_rn(vv[j] - __half2float(h[j]));
    }
    *(uint2*)(g_Ehi + i4) = *(uint2*)h;
    *(uint2*)(g_Elo + i4) = *(uint2*)l;
}
__global__ void prep_e2(const float* __restrict__ emb) {
    int k = blockIdx.x * blockDim.x + threadIdx.x;
    if (k < NCODES) {
        const float* row = emb + (size_t)k * KDIM;
        float s = 0.f;
#pragma unroll 8
        for (int i = 0; i < KDIM; i++) s += row[i] * row[i];
        g_e2[k] = s;
    }
}

// ---------------- main kernel ----------------
__global__ __launch_bounds__(256, 1) void vq_mma_kernel(
    const float* __restrict__ z, float* __restrict__ out)
{
    extern __shared__ char sm[];
    const uint32_t sbase = (uint32_t)__cvta_generic_to_shared(sm);

    const int tid  = threadIdx.x;
    const int lane = tid & 31;
    const int wid  = tid >> 5;
    const int wm   = wid >> 2;          // 0..1 : rows wm*64..+63
    const int wn   = wid & 3;           // 0..3 : cols wn*32..+31
    const int gr   = lane >> 2;
    const int lc   = lane & 3;

    float* e2s = (float*)(sm + E2_OFF);
    unsigned long long* minkey = (unsigned long long*)(sm + MK_OFF);

    // stage e2, init minkey
    for (int i = tid; i < NCODES; i += 256) e2s[i] = g_e2[i];
    if (tid < MCTA) minkey[tid] = ~0ULL;

    // ---- convert X slice fp32 -> fp16 hi/lo into smem A (full K, [m][k], stride ASTR)
    const int mbase = blockIdx.x * MCTA;
    const float* zt = z + ((size_t)(mbase >> 12) * KDIM * NPIX) + (mbase & (NPIX - 1));
    {
        const int m = tid & 127;
        const int half = tid >> 7;                 // covers k in [half*128, half*128+128)
        char* arowh = sm + AHI_OFF + (size_t)m * (ASTR * 2);
        char* arowl = sm + ALO_OFF + (size_t)m * (ASTR * 2);
#pragma unroll 4
        for (int j = 0; j < 64; j++) {
            int k0 = half * 128 + j * 2;
            float v0 = zt[(size_t)k0 * NPIX + m];
            float v1 = zt[(size_t)(k0 + 1) * NPIX + m];
            __half h0 = __float2half_rn(v0), h1 = __float2half_rn(v1);
            __half l0 = __float2half_rn(v0 - __half2float(h0));
            __half l1 = __float2half_rn(v1 - __half2float(h1));
            *(uint32_t*)(arowh + k0 * 2) = (uint32_t)__half_as_ushort(h0) | ((uint32_t)__half_as_ushort(h1) << 16);
            *(uint32_t*)(arowl + k0 * 2) = (uint32_t)__half_as_ushort(l0) | ((uint32_t)__half_as_ushort(l1) << 16);
        }
    }
    __syncthreads();

    // B tile loader: 128 codes x 64 halves, 4 x 16B cp.async per thread
    auto loadB = [&](int nch, int kt, int buf) {
        int seg = kt >> 2;
        int k0  = (kt & 3) * BK;
        const __half* esrc = (seg == 2 ? g_Elo : g_Ehi);
        uint32_t bb = sbase + (buf ? B1_OFF : B0_OFF);
#pragma unroll
        for (int j = 0; j < 4; j++) {
            int chunk = tid * 4 + j;
            int row = chunk >> 3, ch = chunk & 7;
            const __half* src = esrc + (size_t)(nch * 128 + row) * KDIM + k0 + ch * 8;
            cp16(bb + row * (BSTR * 2) + ch * 16, src);
        }
        CP_COMMIT();
    };

    // ldmatrix lane addresses (constant per thread)
    const uint32_t a_lrow = (lane & 15);
    const uint32_t a_lq   = (lane >> 4) * 16;
    const uint32_t b_lrow = (lane & 7) + ((lane & 16) >> 1);
    const uint32_t b_lq   = ((lane >> 3) & 1) * 16;

    for (int nch = 0; nch < 8; nch++) {
        float c[4][4][4];
#pragma unroll
        for (int mi = 0; mi < 4; mi++)
#pragma unroll
            for (int ni = 0; ni < 4; ni++)
#pragma unroll
                for (int r = 0; r < 4; r++) c[mi][ni][r] = 0.f;

        loadB(nch, 0, 0);

        for (int kt = 0; kt < KT; kt++) {
            if (kt + 1 < KT) { loadB(nch, kt + 1, (kt + 1) & 1); CP_WAIT1(); }
            else             { CP_WAIT0(); }
            __syncthreads();

            const int seg = kt >> 2;
            const uint32_t abase = sbase + (seg == 1 ? ALO_OFF : AHI_OFF);
            const uint32_t akb   = (uint32_t)((kt & 3) * BK * 2);
            const uint32_t bbase = sbase + ((kt & 1) ? B1_OFF : B0_OFF);

#pragma unroll
            for (int k16 = 0; k16 < 4; k16++) {
                uint32_t af[4][4];
#pragma unroll
                for (int mi = 0; mi < 4; mi++) {
                    uint32_t addr = abase
                        + (uint32_t)(wm * 64 + mi * 16 + a_lrow) * (ASTR * 2)
                        + akb + (uint32_t)k16 * 32 + a_lq;
                    ldmx4(af[mi], addr);
                }
                uint32_t bf[2][4];
#pragma unroll
                for (int ni2 = 0; ni2 < 2; ni2++) {
                    uint32_t addr = bbase
                        + (uint32_t)(wn * 32 + ni2 * 16 + b_lrow) * (BSTR * 2)
                        + (uint32_t)k16 * 32 + b_lq;
                    ldmx4(bf[ni2], addr);
                }
#pragma unroll
                for (int mi = 0; mi < 4; mi++)
#pragma unroll
                    for (int ni = 0; ni < 4; ni++)
                        mma16816(c[mi][ni], af[mi], bf[ni >> 1][(ni & 1) * 2], bf[ni >> 1][(ni & 1) * 2 + 1]);
            }
            __syncthreads();
        }

        // ---- fused argmin epilogue for this 128-code chunk
#pragma unroll
        for (int mi = 0; mi < 4; mi++) {
#pragma unroll
            for (int rh = 0; rh < 2; rh++) {
                int row = wm * 64 + mi * 16 + gr + rh * 8;
                unsigned long long best = ~0ULL;
#pragma unroll
                for (int ni = 0; ni < 4; ni++) {
#pragma unroll
                    for (int cp = 0; cp < 2; cp++) {
                        float s = c[mi][ni][rh * 2 + cp];
                        int code = nch * 128 + wn * 32 + ni * 8 + lc * 2 + cp;
                        float d = fmaf(-2.f, s, e2s[code]);
                        uint32_t b = __float_as_uint(d);
                        b = (b & 0x80000000u) ? ~b : (b | 0x80000000u);
                        unsigned long long key = ((unsigned long long)b << 32) | (unsigned)code;
                        if (key < best) best = key;
                    }
                }
                atomicMin(&minkey[row], best);
            }
        }
        __syncthreads();
    }

    if (tid < MCTA)
        out[mbase + tid] = (float)(unsigned)(minkey[tid] & 0xFFFFFFFFull);
}

extern "C" void kernel_launch(void* const* d_in, const int* in_sizes, int n_in,
                              void* d_out, int out_size) {
    const float* z;
    const float* emb;
    if (n_in >= 2 && in_sizes[1] > in_sizes[0]) {
        z = (const float*)d_in[1];  emb = (const float*)d_in[0];
    } else {
        z = (const float*)d_in[0];  emb = (const float*)d_in[n_in > 1 ? 1 : 0];
    }
    float* out = (float*)d_out;

    cudaFuncSetAttribute(vq_mma_kernel, cudaFuncAttributeMaxDynamicSharedMemorySize, SMEM_SZ);

    prep_split<<<256, 256>>>(emb);
    prep_e2<<<4, 256>>>(emb);
    vq_mma_kernel<<<65536 / MCTA, 256, SMEM_SZ>>>(z, out);
}